// round 1
// baseline (speedup 1.0000x reference)
#include <cuda_runtime.h>

#define T_LEN 1024
#define N_IN  512
#define BATCH 32
#define BN    (BATCH * N_IN)

// One thread per (b, n) channel. Sequential over T with double-buffered
// prefetch of current/v_th (loads are independent of the recurrence).
// Outputs concatenated: gz[T,B,N], z[T,B,N], m_last[B,N].
__global__ void __launch_bounds__(128, 1) snn_lif_kernel(
    const float* __restrict__ current,
    const float* __restrict__ beta,
    const float* __restrict__ v_init,
    const float* __restrict__ v_th,
    float* __restrict__ out)
{
    const int bn = blockIdx.x * blockDim.x + threadIdx.x;
    if (bn >= BN) return;

    const int n = bn & (N_IN - 1);
    const float b  = beta[n];
    float m  = v_init[bn];
    float s1 = 0.0f;   // cumsum of spikes (exact small integers)
    float z  = 0.0f;   // double cumsum (exact, < 2^24)

    float* __restrict__ gz_out = out;
    float* __restrict__ z_out  = out + (size_t)T_LEN * BN;
    float* __restrict__ m_out  = out + 2ull * T_LEN * BN;

    constexpr int U = 8;
    float cbuf[2][U];
    float vbuf[2][U];

    // Prefetch chunk 0 (front-batched LDGs -> high MLP).
    #pragma unroll
    for (int i = 0; i < U; i++) {
        cbuf[0][i] = current[(size_t)i * BN + bn];
        vbuf[0][i] = v_th   [(size_t)i * BN + bn];
    }

    int buf = 0;
    for (int t0 = 0; t0 < T_LEN; t0 += U) {
        const int nbuf = buf ^ 1;
        if (t0 + U < T_LEN) {
            // Prefetch next chunk while computing this one.
            #pragma unroll
            for (int i = 0; i < U; i++) {
                cbuf[nbuf][i] = current[(size_t)(t0 + U + i) * BN + bn];
                vbuf[nbuf][i] = v_th   [(size_t)(t0 + U + i) * BN + bn];
            }
        }
        #pragma unroll
        for (int i = 0; i < U; i++) {
            m = fmaf(b, m, cbuf[buf][i]);
            const float spike = (m >= vbuf[buf][i]) ? 1.0f : 0.0f;
            s1 += spike;
            z  += s1;
            const size_t o = (size_t)(t0 + i) * BN + bn;
            z_out[o]  = z;
            gz_out[o] = (z == 1.0f) ? 1.0f : 0.0f;
        }
        buf = nbuf;
    }
    m_out[bn] = m;
}

extern "C" void kernel_launch(void* const* d_in, const int* in_sizes, int n_in,
                              void* d_out, int out_size)
{
    const float* current = (const float*)d_in[0];
    const float* beta    = (const float*)d_in[1];
    const float* v_init  = (const float*)d_in[2];
    const float* v_th    = (const float*)d_in[3];
    float* out = (float*)d_out;

    snn_lif_kernel<<<BN / 128, 128>>>(current, beta, v_init, v_th, out);
}

// round 2
// speedup vs baseline: 2.4984x; 2.4984x over previous
#include <cuda_runtime.h>
#include <cstdint>

#define T_LEN 1024
#define N_IN  512
#define BATCH 32
#define BN    (BATCH * N_IN)          // 16384 channels
#define CH_PER_BLK 64
#define NBLOCKS (BN / CH_PER_BLK)     // 256
#define TILE_T 64
#define NTILES (T_LEN / TILE_T)       // 16
#define STAGES 3
#define ROW_BYTES (CH_PER_BLK * 4)            // 256 B per t-row per tensor
#define TILE_BYTES (TILE_T * ROW_BYTES)       // 16 KB per tensor per tile
#define STAGE_BYTES (2 * TILE_BYTES)          // cur + vth
#define SMEM_BYTES (STAGES * STAGE_BYTES)     // 96 KB

__device__ __forceinline__ void cp16(uint32_t dst, const void* src) {
    asm volatile("cp.async.cg.shared.global [%0], [%1], 16;\n"
                 :: "r"(dst), "l"(src) : "memory");
}
__device__ __forceinline__ void cp_commit() {
    asm volatile("cp.async.commit_group;\n" ::: "memory");
}
__device__ __forceinline__ void cp_wait1() {
    asm volatile("cp.async.wait_group 1;\n" ::: "memory");
}

// LIF membrane recurrence + spike + double-cumsum + gate, streamed via a
// 3-stage cp.async SMEM pipeline (in-flight bytes live in SMEM, not regs).
__global__ void __launch_bounds__(CH_PER_BLK, 2) snn_lif_pipe_kernel(
    const float* __restrict__ current,
    const float* __restrict__ beta,
    const float* __restrict__ v_init,
    const float* __restrict__ v_th,
    float* __restrict__ out)
{
    extern __shared__ float smem[];   // [STAGES][2][TILE_T][CH_PER_BLK]

    const int tid = threadIdx.x;
    const int bn0 = blockIdx.x * CH_PER_BLK;
    const int bn  = bn0 + tid;

    // Per-thread cp.async source/dst mapping:
    // chunk id within a tile-tensor = j*64 + tid  (j = 0..15)
    //   row (t within tile) = j*4 + (tid>>4), col bytes = (tid&15)*16
    // dst linear offset = j*1024 + tid*16
    const size_t thr_off = (size_t)(tid >> 4) * BN * 4
                         + (size_t)bn0 * 4
                         + (size_t)(tid & 15) * 16;

    uint32_t smem_u32;
    {
        void* p = smem;
        asm("{ .reg .u64 t; cvta.to.shared.u64 t, %1; cvt.u32.u64 %0, t; }"
            : "=r"(smem_u32) : "l"(p));
    }

    auto issue_tile = [&](int tile) {
        if (tile < NTILES) {
            const size_t toff = (size_t)tile * TILE_T * BN * 4 + thr_off;
            const uint32_t d = smem_u32 + (uint32_t)((tile % STAGES) * STAGE_BYTES)
                             + (uint32_t)tid * 16;
            const char* cs = (const char*)current + toff;
            const char* vs = (const char*)v_th   + toff;
            #pragma unroll
            for (int j = 0; j < 16; ++j) {
                cp16(d + j * 1024,              cs + (size_t)j * 4 * BN * 4);
                cp16(d + TILE_BYTES + j * 1024, vs + (size_t)j * 4 * BN * 4);
            }
        }
        cp_commit();   // empty groups past the end keep wait_group accounting valid
    };

    // Prologue: 2 tiles in flight.
    issue_tile(0);
    issue_tile(1);

    const float b = beta[bn & (N_IN - 1)];
    float m  = v_init[bn];
    float s1 = 0.0f;   // cumsum of spikes (exact small ints in f32)
    float z  = 0.0f;   // double cumsum (max ~5e5 < 2^24, exact)

    float* __restrict__ gz_p = out + bn;
    float* __restrict__ z_p  = out + (size_t)T_LEN * BN + bn;

    for (int tile = 0; tile < NTILES; ++tile) {
        cp_wait1();          // tile's group complete (<=1 group pending)
        __syncthreads();     // make all threads' cp.async data visible

        const float* cs = smem + (size_t)(tile % STAGES) * (STAGE_BYTES / 4);
        const float* vs = cs + (TILE_BYTES / 4);

        #pragma unroll 16
        for (int tt = 0; tt < TILE_T; ++tt) {
            const float c  = cs[tt * CH_PER_BLK + tid];
            const float vt = vs[tt * CH_PER_BLK + tid];
            m = fmaf(b, m, c);
            s1 += (m >= vt) ? 1.0f : 0.0f;
            z  += s1;
            *z_p  = z;
            *gz_p = (z == 1.0f) ? 1.0f : 0.0f;
            z_p  += BN;
            gz_p += BN;
        }

        issue_tile(tile + 2);   // refill the stage freed two tiles ago
    }

    out[2ull * T_LEN * BN + bn] = m;
}

extern "C" void kernel_launch(void* const* d_in, const int* in_sizes, int n_in,
                              void* d_out, int out_size)
{
    const float* current = (const float*)d_in[0];
    const float* beta    = (const float*)d_in[1];
    const float* v_init  = (const float*)d_in[2];
    const float* v_th    = (const float*)d_in[3];
    float* out = (float*)d_out;

    cudaFuncSetAttribute(snn_lif_pipe_kernel,
                         cudaFuncAttributeMaxDynamicSharedMemorySize, SMEM_BYTES);
    snn_lif_pipe_kernel<<<NBLOCKS, CH_PER_BLK, SMEM_BYTES>>>(
        current, beta, v_init, v_th, out);
}